// round 5
// baseline (speedup 1.0000x reference)
#include <cuda_runtime.h>
#include <cuda_bf16.h>

#define B_ROWS   16384
#define CWIN     10
#define KNEG     10
#define NSCORE   (KNEG + 1)
#define DIM      128
#define VEC      (DIM / 4)          // 32 float4 per row -> 1 per lane
#define ROWS_PER_BLOCK 8
#define NTHREADS 256
#define NBLOCKS  (B_ROWS / ROWS_PER_BLOCK)   // 2048
#define EPS      1e-9f

// Scratch for deterministic reduction (no allocations allowed).
__device__ float        g_block_partial[NBLOCKS];
__device__ unsigned int g_done_counter = 0u;

__global__ __launch_bounds__(NTHREADS, 2) void cbow_loss_kernel(
    const int*   __restrict__ ctx,      // [B, CWIN]
    const int*   __restrict__ tgt,      // [B]
    const int*   __restrict__ neg,      // [B, KNEG]
    const float* __restrict__ in_emb,   // [VOCAB, DIM]
    const float* __restrict__ out_emb,  // [VOCAB, DIM]
    float*       __restrict__ out)
{
    const int warp = threadIdx.x >> 5;
    const int lane = threadIdx.x & 31;
    const int row  = blockIdx.x * ROWS_PER_BLOCK + warp;

    const float4* __restrict__ in4  = (const float4*)in_emb;
    const float4* __restrict__ out4 = (const float4*)out_emb;

    // ---- load all indices first (warp-uniform, L1-resident) ----
    int cidx[CWIN], nidx[KNEG], tidx;
#pragma unroll
    for (int i = 0; i < CWIN; i++) cidx[i] = __ldg(&ctx[row * CWIN + i]);
    tidx = __ldg(&tgt[row]);
#pragma unroll
    for (int k = 0; k < KNEG; k++) nidx[k] = __ldg(&neg[row * KNEG + k]);

    // ---- front-batch ALL 21 independent row gathers (max MLP) ----
    float4 cv[CWIN];
#pragma unroll
    for (int i = 0; i < CWIN; i++)
        cv[i] = __ldg(&in4[(size_t)cidx[i] * VEC + lane]);

    float4 ov[NSCORE];
    ov[0] = __ldg(&out4[(size_t)tidx * VEC + lane]);
#pragma unroll
    for (int k = 0; k < KNEG; k++)
        ov[1 + k] = __ldg(&out4[(size_t)nidx[k] * VEC + lane]);

    // ---- context mean ----
    float4 acc = cv[0];
#pragma unroll
    for (int i = 1; i < CWIN; i++) {
        acc.x += cv[i].x; acc.y += cv[i].y; acc.z += cv[i].z; acc.w += cv[i].w;
    }
    const float inv = 1.0f / (float)CWIN;
    acc.x *= inv; acc.y *= inv; acc.z *= inv; acc.w *= inv;

    // ---- 11 dot-product partial scores ----
    float s[NSCORE];
#pragma unroll
    for (int j = 0; j < NSCORE; j++) {
        s[j] = acc.x * ov[j].x + acc.y * ov[j].y
             + acc.z * ov[j].z + acc.w * ov[j].w;
    }

    // ---- warp reductions (butterfly) ----
#pragma unroll
    for (int j = 0; j < NSCORE; j++) {
#pragma unroll
        for (int off = 16; off > 0; off >>= 1)
            s[j] += __shfl_xor_sync(0xffffffffu, s[j], off);
    }

    // ---- per-row loss: spread 11 transcendental terms across lanes 0..10 ----
    // pos (j==0): log(sigmoid(+s0)+eps) = log(1/(1+e^{-s0}) + eps)
    // neg:        log(sigmoid(-sj)+eps) = log(1/(1+e^{+sj}) + eps)
    float term = 0.f;
    if (lane < NSCORE) {
        float x = (lane == 0) ? -s[0] : s[lane];
        term = __logf(__frcp_rn(1.0f + __expf(x)) + EPS);
    }
#pragma unroll
    for (int off = 8; off > 0; off >>= 1)
        term += __shfl_xor_sync(0xffffffffu, term, off);
    // lane 0 now holds sum over lanes 0..15 (lanes 11..15 contribute 0)

    __shared__ float sh[ROWS_PER_BLOCK];
    if (lane == 0) sh[warp] = term;
    __syncthreads();

    __shared__ bool amLast;
    if (threadIdx.x == 0) {
        float t = 0.f;
#pragma unroll
        for (int w = 0; w < ROWS_PER_BLOCK; w++) t += sh[w];
        g_block_partial[blockIdx.x] = t;
        __threadfence();
        unsigned prev = atomicAdd(&g_done_counter, 1u);
        amLast = (prev == NBLOCKS - 1);
    }
    __syncthreads();

    // ---- last block: deterministic final reduction over fixed index order ----
    if (amLast) {
        float t = 0.f;
        for (int i = threadIdx.x; i < NBLOCKS; i += NTHREADS)
            t += __ldcg(&g_block_partial[i]);
#pragma unroll
        for (int off = 16; off > 0; off >>= 1)
            t += __shfl_xor_sync(0xffffffffu, t, off);

        __shared__ float shf[NTHREADS / 32];
        if (lane == 0) shf[warp] = t;
        __syncthreads();
        if (threadIdx.x == 0) {
            float total = 0.f;
#pragma unroll
            for (int w = 0; w < NTHREADS / 32; w++) total += shf[w];
            out[0] = -total / (float)B_ROWS;
            g_done_counter = 0u;   // reset for next graph replay
        }
    }
}

extern "C" void kernel_launch(void* const* d_in, const int* in_sizes, int n_in,
                              void* d_out, int out_size)
{
    const int*   ctx     = (const int*)d_in[0];   // context [B, CWIN]
    const int*   tgt     = (const int*)d_in[1];   // target [B]
    const int*   neg     = (const int*)d_in[2];   // negatives [B, KNEG]
    const float* in_emb  = (const float*)d_in[3]; // [VOCAB, DIM]
    const float* out_emb = (const float*)d_in[4]; // [VOCAB, DIM]
    float*       out     = (float*)d_out;

    cbow_loss_kernel<<<NBLOCKS, NTHREADS>>>(ctx, tgt, neg, in_emb, out_emb, out);
}

// round 7
// speedup vs baseline: 1.4901x; 1.4901x over previous
#include <cuda_runtime.h>
#include <cuda_bf16.h>

#define B_ROWS   16384
#define CWIN     10
#define KNEG     10
#define NSCORE   (KNEG + 1)
#define DIM      128
#define VEC      (DIM / 4)          // 32 float4 per row -> 1 per lane
#define ROWS_PER_WARP  2
#define WARPS_PER_BLOCK 8
#define ROWS_PER_BLOCK (ROWS_PER_WARP * WARPS_PER_BLOCK)   // 16
#define NTHREADS 256
#define NBLOCKS  (B_ROWS / ROWS_PER_BLOCK)                 // 1024
#define EPS      1e-9f

// Scratch for deterministic reduction (no allocations allowed).
__device__ float        g_block_partial[NBLOCKS];
__device__ unsigned int g_done_counter = 0u;

__global__ __launch_bounds__(NTHREADS, 4) void cbow_loss_kernel(
    const int*   __restrict__ ctx,      // [B, CWIN]
    const int*   __restrict__ tgt,      // [B]
    const int*   __restrict__ neg,      // [B, KNEG]
    const float* __restrict__ in_emb,   // [VOCAB, DIM]
    const float* __restrict__ out_emb,  // [VOCAB, DIM]
    float*       __restrict__ out)
{
    const int warp = threadIdx.x >> 5;
    const int lane = threadIdx.x & 31;
    const int row0 = (blockIdx.x * WARPS_PER_BLOCK + warp) * ROWS_PER_WARP;
    const int row1 = row0 + 1;

    const float4* __restrict__ in4  = (const float4*)in_emb;
    const float4* __restrict__ out4 = (const float4*)out_emb;

    // ---- context mean: two interleaved independent chains ----
    float4 a0 = make_float4(0.f, 0.f, 0.f, 0.f);
    float4 a1 = make_float4(0.f, 0.f, 0.f, 0.f);
#pragma unroll
    for (int i = 0; i < CWIN; i++) {
        int i0 = __ldg(&ctx[row0 * CWIN + i]);
        int i1 = __ldg(&ctx[row1 * CWIN + i]);
        float4 v0 = __ldg(&in4[(size_t)i0 * VEC + lane]);
        float4 v1 = __ldg(&in4[(size_t)i1 * VEC + lane]);
        a0.x += v0.x; a0.y += v0.y; a0.z += v0.z; a0.w += v0.w;
        a1.x += v1.x; a1.y += v1.y; a1.z += v1.z; a1.w += v1.w;
    }
    const float inv = 1.0f / (float)CWIN;
    a0.x *= inv; a0.y *= inv; a0.z *= inv; a0.w *= inv;
    a1.x *= inv; a1.y *= inv; a1.z *= inv; a1.w *= inv;

    // ---- 11 dot-product partial scores per row, interleaved ----
    float s0[NSCORE], s1[NSCORE];
    {
        int t0 = __ldg(&tgt[row0]);
        int t1 = __ldg(&tgt[row1]);
        float4 v0 = __ldg(&out4[(size_t)t0 * VEC + lane]);
        float4 v1 = __ldg(&out4[(size_t)t1 * VEC + lane]);
        s0[0] = a0.x * v0.x + a0.y * v0.y + a0.z * v0.z + a0.w * v0.w;
        s1[0] = a1.x * v1.x + a1.y * v1.y + a1.z * v1.z + a1.w * v1.w;
    }
#pragma unroll
    for (int k = 0; k < KNEG; k++) {
        int i0 = __ldg(&neg[row0 * KNEG + k]);
        int i1 = __ldg(&neg[row1 * KNEG + k]);
        float4 v0 = __ldg(&out4[(size_t)i0 * VEC + lane]);
        float4 v1 = __ldg(&out4[(size_t)i1 * VEC + lane]);
        s0[1 + k] = a0.x * v0.x + a0.y * v0.y + a0.z * v0.z + a0.w * v0.w;
        s1[1 + k] = a1.x * v1.x + a1.y * v1.y + a1.z * v1.z + a1.w * v1.w;
    }

    // ---- warp reductions (butterfly), both rows ----
#pragma unroll
    for (int j = 0; j < NSCORE; j++) {
#pragma unroll
        for (int off = 16; off > 0; off >>= 1) {
            s0[j] += __shfl_xor_sync(0xffffffffu, s0[j], off);
            s1[j] += __shfl_xor_sync(0xffffffffu, s1[j], off);
        }
    }

    // ---- per-row loss terms spread across lanes:
    //      lanes 0..10 -> row0 terms, lanes 16..26 -> row1 terms ----
    // pos (j==0): log(sigmoid(+s)+eps) = log(1/(1+e^{-s}) + eps)
    // neg:        log(sigmoid(-s)+eps) = log(1/(1+e^{+s}) + eps)
    float term = 0.f;
    {
        int lj = lane & 15;
        bool hi = (lane >= 16);
        if (lj < NSCORE) {
            float sv = hi ? s1[lj] : s0[lj];
            float x  = (lj == 0) ? -sv : sv;
            term = __logf(__frcp_rn(1.0f + __expf(x)) + EPS);
        }
    }
    // fold lanes 0..15 -> lane 0 (row0), lanes 16..31 -> lane 16 (row1)
#pragma unroll
    for (int off = 8; off > 0; off >>= 1)
        term += __shfl_xor_sync(0xffffffffu, term, off);
    // combine row1 into lane 0
    term += __shfl_xor_sync(0xffffffffu, term, 16);

    __shared__ float sh[WARPS_PER_BLOCK];
    if (lane == 0) sh[warp] = term;
    __syncthreads();

    __shared__ bool amLast;
    if (threadIdx.x == 0) {
        float t = 0.f;
#pragma unroll
        for (int w = 0; w < WARPS_PER_BLOCK; w++) t += sh[w];
        g_block_partial[blockIdx.x] = t;
        __threadfence();
        unsigned prev = atomicAdd(&g_done_counter, 1u);
        amLast = (prev == NBLOCKS - 1);
    }
    __syncthreads();

    // ---- last block: deterministic final reduction, fixed index order ----
    if (amLast) {
        float t = 0.f;
        for (int i = threadIdx.x; i < NBLOCKS; i += NTHREADS)
            t += __ldcg(&g_block_partial[i]);
#pragma unroll
        for (int off = 16; off > 0; off >>= 1)
            t += __shfl_xor_sync(0xffffffffu, t, off);

        __shared__ float shf[NTHREADS / 32];
        if (lane == 0) shf[warp] = t;
        __syncthreads();
        if (threadIdx.x == 0) {
            float total = 0.f;
#pragma unroll
            for (int w = 0; w < NTHREADS / 32; w++) total += shf[w];
            out[0] = -total / (float)B_ROWS;
            g_done_counter = 0u;   // reset for next graph replay
        }
    }
}

extern "C" void kernel_launch(void* const* d_in, const int* in_sizes, int n_in,
                              void* d_out, int out_size)
{
    const int*   ctx     = (const int*)d_in[0];   // context [B, CWIN]
    const int*   tgt     = (const int*)d_in[1];   // target [B]
    const int*   neg     = (const int*)d_in[2];   // negatives [B, KNEG]
    const float* in_emb  = (const float*)d_in[3]; // [VOCAB, DIM]
    const float* out_emb = (const float*)d_in[4]; // [VOCAB, DIM]
    float*       out     = (float*)d_out;

    cbow_loss_kernel<<<NBLOCKS, NTHREADS>>>(ctx, tgt, neg, in_emb, out_emb, out);
}